// round 3
// baseline (speedup 1.0000x reference)
#include <cuda_runtime.h>
#include <cuda_bf16.h>
#include <cstdint>

#define BSZ 512
#define DIM 128
#define MARGIN 0.2f

// Scratch (no allocations allowed anywhere)
__device__ float g_dist[BSZ * BSZ];
__device__ float g_psum[BSZ];
__device__ int   g_pcnt[BSZ];
__device__ int   g_ctr;          // zero-init; last block resets -> replay-safe

// ---- packed f32x2 helpers (Blackwell) -------------------------------------
__device__ __forceinline__ unsigned long long add2(unsigned long long a,
                                                   unsigned long long b) {
    unsigned long long r;
    asm("add.rn.f32x2 %0, %1, %2;" : "=l"(r) : "l"(a), "l"(b));
    return r;
}
__device__ __forceinline__ unsigned long long fma2(unsigned long long a,
                                                   unsigned long long b,
                                                   unsigned long long c) {
    unsigned long long r;
    asm("fma.rn.f32x2 %0, %1, %2, %3;" : "=l"(r) : "l"(a), "l"(b), "l"(c));
    return r;
}
__device__ __forceinline__ float sum2(unsigned long long v) {
    float lo, hi;
    asm("mov.b64 {%0, %1}, %2;" : "=f"(lo), "=f"(hi) : "l"(v));
    return lo + hi;
}

// ---------------------------------------------------------------------------
// Kernel A: pairwise Euclidean dist, diff-based (matches reference), with
// f32x2 packed sub(=add of negated B)/fma. Tile 32x32, 2x2 micro, all of
// K=128 staged in smem once (single barrier).
// ---------------------------------------------------------------------------
__global__ __launch_bounds__(256, 4)
void dist_kernel(const float* __restrict__ emb) {
    __shared__ float sA[32][130];   // 128 cols + 2 pad (65 ull/row, odd stride)
    __shared__ float sB[32][130];   // stores NEGATED B rows

    const int tx = threadIdx.x, ty = threadIdx.y;
    const int tid = ty * 16 + tx;
    const int i0 = blockIdx.y * 32;
    const int j0 = blockIdx.x * 32;

    // 32 rows x 32 float4 = 1024 float4 per matrix; 4 per thread
    #pragma unroll
    for (int t = tid; t < 1024; t += 256) {
        const int row = t >> 5;
        const int c4  = t & 31;
        const float4 va = *(const float4*)(emb + (size_t)(i0 + row) * DIM + c4 * 4);
        float2* da = (float2*)&sA[row][c4 * 4];
        da[0] = make_float2(va.x, va.y);
        da[1] = make_float2(va.z, va.w);
        const float4 vb = *(const float4*)(emb + (size_t)(j0 + row) * DIM + c4 * 4);
        float2* db = (float2*)&sB[row][c4 * 4];
        db[0] = make_float2(-vb.x, -vb.y);
        db[1] = make_float2(-vb.z, -vb.w);
    }
    __syncthreads();

    const unsigned long long* A0 = (const unsigned long long*)sA[ty * 2 + 0];
    const unsigned long long* A1 = (const unsigned long long*)sA[ty * 2 + 1];
    const unsigned long long* B0 = (const unsigned long long*)sB[tx * 2 + 0];
    const unsigned long long* B1 = (const unsigned long long*)sB[tx * 2 + 1];

    unsigned long long acc00 = 0ull, acc01 = 0ull, acc10 = 0ull, acc11 = 0ull;

    #pragma unroll 16
    for (int k2 = 0; k2 < 64; k2++) {
        const unsigned long long a0 = A0[k2];
        const unsigned long long a1 = A1[k2];
        const unsigned long long b0 = B0[k2];
        const unsigned long long b1 = B1[k2];
        unsigned long long t;
        t = add2(a0, b0); acc00 = fma2(t, t, acc00);
        t = add2(a0, b1); acc01 = fma2(t, t, acc01);
        t = add2(a1, b0); acc10 = fma2(t, t, acc10);
        t = add2(a1, b1); acc11 = fma2(t, t, acc11);
    }

    const int i = i0 + ty * 2;
    const int j = j0 + tx * 2;
    const float s00 = sum2(acc00), s01 = sum2(acc01);
    const float s10 = sum2(acc10), s11 = sum2(acc11);
    g_dist[(size_t)(i + 0) * BSZ + (j + 0)] = s00 > 0.f ? sqrtf(s00) : 0.f;
    g_dist[(size_t)(i + 0) * BSZ + (j + 1)] = s01 > 0.f ? sqrtf(s01) : 0.f;
    g_dist[(size_t)(i + 1) * BSZ + (j + 0)] = s10 > 0.f ? sqrtf(s10) : 0.f;
    g_dist[(size_t)(i + 1) * BSZ + (j + 1)] = s11 > 0.f ? sqrtf(s11) : 0.f;
}

// ---------------------------------------------------------------------------
// Kernel B: warp-per-row mining + fused deterministic finalize.
// For each valid pair (i<p, same label):
//   j_min = first j: neg[j] && d_ap < d[i,j] < d_ap+margin
//   found  -> d_an = d[i, rank(j_min)]   (reference quirk: index by neg-rank)
//   !found -> d_an = d[i, j0]            (j0 = first negative, else 0)
//   loss  += relu(d_ap^2 - d_an^2 + margin)
// ---------------------------------------------------------------------------
#define MW 8   // warps (rows) per block

__global__ __launch_bounds__(256, 4)
void mine_kernel(const int* __restrict__ labels, float* __restrict__ out) {
    __shared__ float    sd[MW][BSZ];     // per-warp dist row
    __shared__ int      slab[BSZ];
    __shared__ unsigned snm[MW][16];     // per-warp neg ballot words
    __shared__ int      sLast;

    const int tid  = threadIdx.x;
    const int warp = tid >> 5;
    const int lane = tid & 31;
    const int i    = blockIdx.x * MW + warp;

    for (int t = tid; t < BSZ; t += 256) slab[t] = labels[t];
    __syncthreads();

    // warp-cooperative load of dist row i (coalesced float4)
    {
        const float4* rp = (const float4*)(g_dist + (size_t)i * BSZ);
        float4* sp = (float4*)sd[warp];
        #pragma unroll
        for (int q = 0; q < 4; q++) sp[lane + 32 * q] = rp[lane + 32 * q];
    }

    const int li = slab[i];
    unsigned negm[16];
    float    dv[16];
    #pragma unroll
    for (int c = 0; c < 16; c++) {
        const int j = c * 32 + lane;
        negm[c] = __ballot_sync(0xffffffffu, slab[j] != li);
        dv[c]   = sd[warp][j];
        if (lane == 0) snm[warp][c] = negm[c];
    }
    __syncwarp();

    // fallback: first negative index (argmax of all-False == 0)
    int j0 = -1;
    #pragma unroll
    for (int c = 0; c < 16; c++)
        if (j0 < 0 && negm[c]) j0 = c * 32 + (__ffs(negm[c]) - 1);
    if (j0 < 0) j0 = 0;
    const float dfb = sd[warp][j0];

    float sum = 0.f;
    int   cnt = 0;

    #pragma unroll
    for (int c = 0; c < 16; c++) {
        const unsigned gt = __ballot_sync(0xffffffffu, (c * 32 + lane) > i);
        unsigned pm = (~negm[c]) & gt;        // positives p>i in this chunk
        cnt += __popc(pm);
        while (pm) {                           // warp-uniform loop
            const int b = __ffs(pm) - 1;
            pm &= pm - 1;
            const float dap = sd[warp][c * 32 + b];
            const float hiع = dap + MARGIN;
            int fc = -1, fb = 0;
            #pragma unroll
            for (int c2 = 0; c2 < 16; c2++) {
                if (fc < 0) {
                    const bool cond = ((negm[c2] >> lane) & 1u) &&
                                      dv[c2] > dap && dv[c2] < hiع;
                    const unsigned bm = __ballot_sync(0xffffffffu, cond);
                    if (bm) { fc = c2; fb = __ffs(bm) - 1; }
                }
            }
            float dan;
            if (fc >= 0) {
                int rank = 0;
                for (int c3 = 0; c3 < fc; c3++) rank += __popc(snm[warp][c3]);
                rank += __popc(snm[warp][fc] & ((1u << fb) - 1u));
                dan = sd[warp][rank];          // reference quirk
            } else {
                dan = dfb;
            }
            const float v = fmaf(dap, dap, MARGIN) - dan * dan;
            sum += v > 0.f ? v : 0.f;
        }
    }

    if (lane == 0) {
        g_psum[i] = sum;
        g_pcnt[i] = cnt;
        __threadfence();
    }
    __syncthreads();

    // last-block fused finalize (fixed-order -> deterministic)
    if (tid == 0) {
        const int prev = atomicAdd(&g_ctr, 1);
        sLast = (prev == gridDim.x - 1) ? 1 : 0;
    }
    __syncthreads();
    if (sLast) {
        __threadfence();
        __shared__ float rs[256];
        __shared__ int   rc[256];
        rs[tid] = g_psum[tid] + g_psum[tid + 256];
        rc[tid] = g_pcnt[tid] + g_pcnt[tid + 256];
        __syncthreads();
        #pragma unroll
        for (int s = 128; s > 0; s >>= 1) {
            if (tid < s) { rs[tid] += rs[tid + s]; rc[tid] += rc[tid + s]; }
            __syncthreads();
        }
        if (tid == 0) {
            out[0] = rs[0] / (float)rc[0];
            g_ctr  = 0;                       // reset for next graph replay
        }
    }
}

// ---------------------------------------------------------------------------
extern "C" void kernel_launch(void* const* d_in, const int* in_sizes, int n_in,
                              void* d_out, int out_size) {
    const float* emb    = (const float*)d_in[0];
    const int*   labels = (const int*)d_in[1];
    float*       out    = (float*)d_out;

    dim3 gA(16, 16), bA(16, 16);
    dist_kernel<<<gA, bA>>>(emb);
    mine_kernel<<<BSZ / MW, 256>>>(labels, out);
}